// round 16
// baseline (speedup 1.0000x reference)
#include <cuda_runtime.h>
#include <cuda_bf16.h>
#include <cuda_fp16.h>

#define BB 16
#define TT 2048
#define CC 288
#define HS 32
#define NROWS (BB*TT)
#define NKS (CC/16)
#define QKSCALE 0.17677669529663687f

typedef unsigned long long u64;
typedef unsigned int u32;

// ---- scratch (device globals; cudaMalloc forbidden) ----
__device__ __align__(16) __nv_bfloat16 g_kspl[NROWS*64];
__device__ __align__(16) __nv_bfloat16 g_qspl[NROWS*64];
__device__ __align__(16) __half g_vth[BB*HS*TT];   // V^T hi (fp16)
__device__ __align__(16) __half g_vtl[BB*HS*TT];   // V^T lo (fp16)
__device__ u64 g_wbh[3*NKS*32*4];
__device__ u64 g_wbl[3*NKS*32*4];
__device__ float g_pacc[(size_t)4*NROWS*HS];   // split-s partial P.V
__device__ float g_pden[NROWS*4];              // [row][slot] partial sum(exp)
__device__ int   g_cnt[256];                   // [b][tile] completion counters

__device__ __forceinline__ u32 packbf(__nv_bfloat16 a, __nv_bfloat16 b) {
    return ((u32)__bfloat16_as_ushort(b) << 16) | (u32)__bfloat16_as_ushort(a);
}
__device__ __forceinline__ u32 smem_u32(const void* p) {
    u32 a; asm("{ .reg .u64 t; cvta.to.shared.u64 t, %1; cvt.u32.u64 %0, t; }" : "=r"(a) : "l"(p));
    return a;
}
__device__ __forceinline__ u32 cvt2f16(float hi, float lo) {
    u32 r; asm("cvt.rn.f16x2.f32 %0,%1,%2;" : "=r"(r) : "f"(hi), "f"(lo)); return r;
}
__device__ __forceinline__ void mma_bf16(float* d, const u32* a, const u32* b) {
    asm volatile(
        "mma.sync.aligned.m16n8k16.row.col.f32.bf16.bf16.f32 "
        "{%0,%1,%2,%3}, {%4,%5,%6,%7}, {%8,%9}, {%0,%1,%2,%3};"
        : "+f"(d[0]), "+f"(d[1]), "+f"(d[2]), "+f"(d[3])
        : "r"(a[0]), "r"(a[1]), "r"(a[2]), "r"(a[3]), "r"(b[0]), "r"(b[1]));
}
__device__ __forceinline__ void mma_fp16(float* d, const u32* a, const u32* b) {
    asm volatile(
        "mma.sync.aligned.m16n8k16.row.col.f32.f16.f16.f32 "
        "{%0,%1,%2,%3}, {%4,%5,%6,%7}, {%8,%9}, {%0,%1,%2,%3};"
        : "+f"(d[0]), "+f"(d[1]), "+f"(d[2]), "+f"(d[3])
        : "r"(a[0]), "r"(a[1]), "r"(a[2]), "r"(a[3]), "r"(b[0]), "r"(b[1]));
}
__device__ __forceinline__ void ldsm4(u32& r0, u32& r1, u32& r2, u32& r3, u32 addr) {
    asm volatile("ldmatrix.sync.aligned.m8n8.x4.shared.b16 {%0,%1,%2,%3}, [%4];"
                 : "=r"(r0), "=r"(r1), "=r"(r2), "=r"(r3) : "r"(addr));
}
__device__ __forceinline__ void cpa16(u32 dst, const void* src) {
    asm volatile("cp.async.cg.shared.global [%0], [%1], 16;" :: "r"(dst), "l"(src));
}
#define CPCOMMIT() asm volatile("cp.async.commit_group;" ::: "memory")
#define CPWAIT0()  asm volatile("cp.async.wait_group 0;" ::: "memory")

// ---- (tile, chunk<<8) worklist: heavy 4-unit chunks first. Flat grid 640:
// wave 1 = heavy blocks only, wave 2 = light partials.
static __device__ const int g_pairs[40] = {
    15, 15|256, 15|512, 15|768,
    14, 14|256, 14|512,
    13, 13|256, 13|512,
    12, 12|256, 12|512,
    11, 11|256, 11|512,
    10, 10|256, 9, 9|256, 8, 8|256, 7, 7|256,
    6, 5, 4, 3,
    14|768, 10|512, 6|256, 2,
    13|768, 9|512, 5|256, 1,
    12|768, 8|512, 4|256, 0
};

// -------------------------------------------------------------------------
// Prepack: W -> bf16 hi/lo B-fragment u64s + zero combine counters.
// -------------------------------------------------------------------------
__global__ void prepack_kernel(const float* __restrict__ Wk,
                               const float* __restrict__ Wq,
                               const float* __restrict__ Wv) {
    if (blockIdx.x == 0) g_cnt[threadIdx.x] = 0;
    int i = blockIdx.x * 256 + threadIdx.x;
    if (i >= 3 * NKS * 32 * 4) return;
    int tig = i & 3;
    int n = (i >> 2) & 31;
    int ks = (i >> 7) % NKS;
    int p = i / (NKS * 32 * 4);
    const float* W = (p == 0) ? Wk : (p == 1) ? Wq : Wv;
    float s = (p == 0) ? QKSCALE : 1.0f;
    int c0 = ks * 16 + tig * 2;
    float w[4];
    w[0] = W[(c0)     * HS + n] * s;
    w[1] = W[(c0 + 1) * HS + n] * s;
    w[2] = W[(c0 + 8) * HS + n] * s;
    w[3] = W[(c0 + 9) * HS + n] * s;
    __nv_bfloat16 h[4]; float l[4];
#pragma unroll
    for (int j = 0; j < 4; j++) { h[j] = __float2bfloat16(w[j]); l[j] = w[j] - __bfloat162float(h[j]); }
    g_wbh[i] = ((u64)packbf(h[2], h[3]) << 32) | (u64)packbf(h[0], h[1]);
    g_wbl[i] = ((u64)packbf(__float2bfloat16(l[2]), __float2bfloat16(l[3])) << 32)
             | (u64)packbf(__float2bfloat16(l[0]), __float2bfloat16(l[1]));
}

// -------------------------------------------------------------------------
// Tensor-core projection (unchanged; K/Q bf16 hi/lo, V fp16 hi/lo).
// -------------------------------------------------------------------------
#define XSTR 296
#define PSM (64*XSTR*2*2)

__global__ void __launch_bounds__(256, 3) proj_mma(const float* __restrict__ x) {
    extern __shared__ __nv_bfloat16 psm[];
    __nv_bfloat16* xhi = psm;
    __half* vsh = (__half*)psm;          // aliases x region (dead after MMA loop)
    __half* vsl = (__half*)(psm + 2048);

    int tid = threadIdx.x;
    int row0 = blockIdx.x * 64;

    {
        const float4* xg = (const float4*)(x + (size_t)row0 * CC);
        for (int i = tid; i < 64 * 72; i += 256) {
            int row = i / 72, c4 = i % 72;
            float4 v = xg[i];
            __nv_bfloat16 h0 = __float2bfloat16(v.x), h1 = __float2bfloat16(v.y);
            __nv_bfloat16 h2 = __float2bfloat16(v.z), h3 = __float2bfloat16(v.w);
            *(uint2*)(xhi + row * XSTR + c4 * 4) =
                make_uint2(packbf(h0, h1), packbf(h2, h3));
            *(uint2*)(xhi + (64 + row) * XSTR + c4 * 4) = make_uint2(
                packbf(__float2bfloat16(v.x - __bfloat162float(h0)),
                       __float2bfloat16(v.y - __bfloat162float(h1))),
                packbf(__float2bfloat16(v.z - __bfloat162float(h2)),
                       __float2bfloat16(v.w - __bfloat162float(h3))));
        }
    }
    __syncthreads();

    int wid = tid >> 5, lane = tid & 31;
    int g = lane >> 2, tig = lane & 3;
    int rs = wid & 3, half = wid >> 2;
    int lr = lane & 7, lm = lane >> 3;

    u32 smb = smem_u32(psm);
    u32 xh_b = smb + (u32)(((rs * 16 + lr + (lm & 1) * 8) * XSTR + (lm >> 1) * 8) * 2);
    u32 xl_b = xh_b + (u32)(64 * XSTR * 2);

    int ou[6];
#pragma unroll
    for (int u = 0; u < 6; u++) {
        int idx = half * 6 + u;
        int p = idx >> 2, nt = idx & 3;
        ou[u] = ((p * NKS) * 32 + nt * 8 + g) * 4 + tig;
    }

    float oacc[6][4];
#pragma unroll
    for (int u = 0; u < 6; u++)
#pragma unroll
        for (int j = 0; j < 4; j++) oacc[u][j] = 0.f;

    for (int ks = 0; ks < NKS; ks++) {
        u32 ah[4], al[4];
        ldsm4(ah[0], ah[1], ah[2], ah[3], xh_b + (u32)(ks * 32));
        ldsm4(al[0], al[1], al[2], al[3], xl_b + (u32)(ks * 32));
        int o2 = ks * 128;
#pragma unroll
        for (int u = 0; u < 6; u++) {
            u64 wh = g_wbh[ou[u] + o2];
            u64 wl = g_wbl[ou[u] + o2];
            u32 bh[2] = { (u32)wh, (u32)(wh >> 32) };
            u32 bl[2] = { (u32)wl, (u32)(wl >> 32) };
            mma_bf16(oacc[u], ah, bh);
            mma_bf16(oacc[u], al, bh);
            mma_bf16(oacc[u], ah, bl);
        }
    }
    __syncthreads();   // x region dead; vsh/vsl alias it below

#pragma unroll
    for (int u = 0; u < 6; u++) {
        int idx = half * 6 + u;
        int p = idx >> 2, nt = idx & 3;
        int c0 = nt * 8 + 2 * tig;
        int rloc0 = rs * 16 + g;
#pragma unroll
        for (int rr = 0; rr < 2; rr++) {
            int rloc = rloc0 + rr * 8;
            float v0 = oacc[u][rr * 2], v1 = oacc[u][rr * 2 + 1];
            if (p == 0) {
                __nv_bfloat16 h0 = __float2bfloat16(v0), h1 = __float2bfloat16(v1);
                size_t r = (size_t)(row0 + rloc) * 64;
                *(u32*)(g_kspl + r + c0) = packbf(h0, h1);
                *(u32*)(g_kspl + r + 32 + c0) =
                    packbf(__float2bfloat16(v0 - __bfloat162float(h0)),
                           __float2bfloat16(v1 - __bfloat162float(h1)));
            } else if (p == 1) {
                __nv_bfloat16 h0 = __float2bfloat16(v0), h1 = __float2bfloat16(v1);
                size_t r = (size_t)(row0 + rloc) * 64;
                *(u32*)(g_qspl + r + c0) = packbf(h0, h1);
                *(u32*)(g_qspl + r + 32 + c0) =
                    packbf(__float2bfloat16(v0 - __bfloat162float(h0)),
                           __float2bfloat16(v1 - __bfloat162float(h1)));
            } else {
                __half h0 = __float2half_rn(v0), h1 = __float2half_rn(v1);
                vsh[c0 * 64 + rloc] = h0;
                vsh[(c0 + 1) * 64 + rloc] = h1;
                vsl[c0 * 64 + rloc] = __float2half_rn(v0 - __half2float(h0));
                vsl[(c0 + 1) * 64 + rloc] = __float2half_rn(v1 - __half2float(h1));
            }
        }
    }
    __syncthreads();
    {
        int b = row0 >> 11, tin = row0 & (TT - 1);
        int h = tid >> 3, seg = tid & 7;
        size_t gb = ((size_t)(b * HS + h)) * TT + tin + seg * 8;
        *(uint4*)(g_vth + gb) = *(const uint4*)(vsh + h * 64 + seg * 8);
        *(uint4*)(g_vtl + gb) = *(const uint4*)(vsl + h * 64 + seg * 8);
    }
}

// -------------------------------------------------------------------------
// Flash attention: QK bf16 3-split, PV fp16 (single-P x V hi/lo).
// Split-s + cp.async double buffering; Q1 aliases K region (70 KB, 3 CTA/SM).
// Single-chunk tiles write out directly; multi-chunk groups reduce in the
// LAST-arriving block (atomic counter, __ldcg reads) -- no combine kernel.
// -------------------------------------------------------------------------
#define KSTR 72
#define VSTR 136
#define QOFS0 9216
#define QOFS1 0
#define VB0   18432
#define VBSZ  8704
#define SMEMB (35840 * 2)

__device__ __forceinline__ void load_tile_async(u32 smb, int buf, int b, int s0, int tid) {
    const uint4* qg = (const uint4*)(g_qspl + ((size_t)(b * TT + s0)) * 64);
    u32 qb = smb + (buf ? (u32)(QOFS1 * 2) : (u32)(QOFS0 * 2));
#pragma unroll
    for (int k = 0; k < 4; k++) {
        int i = tid + k * 256;
        int row = i >> 3, seg = i & 7;
        cpa16(qb + (u32)((row * KSTR + seg * 8) * 2), qg + i);
    }
    u32 vhb = smb + (u32)((VB0 + buf * VBSZ) * 2);
    u32 vlb = vhb + (u32)(4352 * 2);
#pragma unroll
    for (int k = 0; k < 2; k++) {
        int i = tid + k * 256;
        int row = i >> 4, seg = i & 15;
        size_t base = ((size_t)(b * HS + row)) * TT + s0;
        u32 off = (u32)((row * VSTR + seg * 8) * 2);
        cpa16(vhb + off, ((const uint4*)(g_vth + base)) + seg);
        cpa16(vlb + off, ((const uint4*)(g_vtl + base)) + seg);
    }
}

__global__ void __launch_bounds__(256, 3) attn_mma(float* __restrict__ out) {
    extern __shared__ __nv_bfloat16 sm[];
    __shared__ int s_last;
    __nv_bfloat16* ks = sm;        // K region; becomes Q buffer 1

    int pr = g_pairs[blockIdx.x >> 4];
    int b = blockIdx.x & 15;
    int tile = pr & 0xff;
    int slot = pr >> 8;

    int tid = threadIdx.x, wid = tid >> 5, lane = tid & 31;
    int qr = lane >> 2, qc = (lane & 3) << 1;
    int lr = lane & 7, lm = lane >> 3;
    int t0 = tile << 7;
    int r1 = (wid << 4) + qr;
    int trow1 = t0 + r1, trow2 = trow1 + 8;

    u32 smb = smem_u32(sm);
    u32 qcol2 = (lm == 0) ? 0u : (lm == 1) ? 16u : (lm == 2) ? 64u : 80u;
    u32 qlb_off = (u32)(lr * KSTR * 2) + qcol2;
    u32 vlb_off = ((lm & 2) ? (u32)(4352 * 2) : 0u) + (u32)(lr * VSTR * 2) + (u32)((lm & 1) * 16);

    int st_beg = slot * 4;
    int st_end = st_beg + 4;
    if (st_end > tile + 1) st_end = tile + 1;
    int nst = st_end - st_beg;
    bool fullrow = (st_beg == 0) && (st_end == tile + 1);

    // ---- K tile + first Q/V tile async ----
    {
        const uint4* kg = (const uint4*)(g_kspl + ((size_t)(b * TT + t0)) * 64);
        for (int i = tid; i < 1024; i += 256) {
            int row = i >> 3, seg = i & 7;
            *(uint4*)(ks + row * KSTR + seg * 8) = kg[row * 8 + seg];
        }
    }
    load_tile_async(smb, 0, b, st_beg << 7, tid);
    CPCOMMIT();
    __syncthreads();

    u32 aK[2][2][4];
#pragma unroll
    for (int sp = 0; sp < 2; sp++)
#pragma unroll
        for (int kk = 0; kk < 2; kk++) {
            int c = sp * 32 + kk * 16 + qc;
            aK[sp][kk][0] = *(const u32*)(ks + r1 * KSTR + c);
            aK[sp][kk][1] = *(const u32*)(ks + (r1 + 8) * KSTR + c);
            aK[sp][kk][2] = *(const u32*)(ks + r1 * KSTR + c + 8);
            aK[sp][kk][3] = *(const u32*)(ks + (r1 + 8) * KSTR + c + 8);
        }

    float oacc[4][4];
#pragma unroll
    for (int i = 0; i < 4; i++)
#pragma unroll
        for (int j = 0; j < 4; j++) oacc[i][j] = 0.f;
    float den1 = 0.f, den2 = 0.f;

    for (int it = 0; it < nst; it++) {
        int st = st_beg + it;
        int cur = it & 1;
        CPWAIT0();
        __syncthreads();
        if (it + 1 < nst) {
            load_tile_async(smb, cur ^ 1, b, (st + 1) << 7, tid);
            CPCOMMIT();
        }
        u32 qlb = smb + (cur ? (u32)(QOFS1 * 2) : (u32)(QOFS0 * 2)) + qlb_off;
        u32 vlb = smb + (u32)((VB0 + cur * VBSZ) * 2) + vlb_off;

        bool diag = (st == tile);
#pragma unroll 1
        for (int ch = 0; ch < 4; ch++) {
            float sacc[4][4];
#pragma unroll
            for (int i = 0; i < 4; i++)
#pragma unroll
                for (int j = 0; j < 4; j++) sacc[i][j] = 0.f;
#pragma unroll
            for (int kk = 0; kk < 2; kk++) {
#pragma unroll
                for (int nt = 0; nt < 4; nt++) {
                    u32 b0, b1, b2, b3;
                    ldsm4(b0, b1, b2, b3,
                          qlb + (u32)((((ch * 32 + nt * 8) * KSTR) + kk * 16) * 2));
                    u32 bh[2] = { b0, b1 }, bl[2] = { b2, b3 };
                    mma_bf16(sacc[nt], aK[0][kk], bh);
                    mma_bf16(sacc[nt], aK[1][kk], bh);
                    mma_bf16(sacc[nt], aK[0][kk], bl);
                }
            }
            u32 pha[2][4];
            int scb = (st << 7) + ch * 32;
#pragma unroll
            for (int nt = 0; nt < 4; nt++) {
                int c0 = scb + nt * 8 + qc;
                float p0, p1, p2, p3;
                if (diag) {
                    p0 = (c0     <= trow1) ? __expf(sacc[nt][0]) : 0.f;
                    p1 = (c0 + 1 <= trow1) ? __expf(sacc[nt][1]) : 0.f;
                    p2 = (c0     <= trow2) ? __expf(sacc[nt][2]) : 0.f;
                    p3 = (c0 + 1 <= trow2) ? __expf(sacc[nt][3]) : 0.f;
                } else {
                    p0 = __expf(sacc[nt][0]);
                    p1 = __expf(sacc[nt][1]);
                    p2 = __expf(sacc[nt][2]);
                    p3 = __expf(sacc[nt][3]);
                }
                den1 += p0 + p1;
                den2 += p2 + p3;
                int j = nt >> 1, o = (nt & 1) << 1;
                pha[j][o]     = cvt2f16(p1, p0);
                pha[j][o + 1] = cvt2f16(p3, p2);
            }
#pragma unroll
            for (int j = 0; j < 2; j++) {
#pragma unroll
                for (int hnt = 0; hnt < 4; hnt++) {
                    u32 b0, b1, b2, b3;
                    ldsm4(b0, b1, b2, b3,
                          vlb + (u32)((hnt * 8 * VSTR + ch * 32 + j * 16) * 2));
                    u32 bvh[2] = { b0, b1 }, bvl[2] = { b2, b3 };
                    mma_fp16(oacc[hnt], pha[j], bvh);
                    mma_fp16(oacc[hnt], pha[j], bvl);
                }
            }
        }
    }

    den1 += __shfl_xor_sync(0xffffffffu, den1, 1);
    den1 += __shfl_xor_sync(0xffffffffu, den1, 2);
    den2 += __shfl_xor_sync(0xffffffffu, den2, 1);
    den2 += __shfl_xor_sync(0xffffffffu, den2, 2);

    size_t r1g = (size_t)b * TT + trow1;
    size_t r2g = (size_t)b * TT + trow2;
    if (fullrow) {
        // single-chunk tile: normalize and write final output directly
        float rinv1 = 1.f / den1, rinv2 = 1.f / den2;
        float* oa = out + r1g * HS;
        float* ob = out + r2g * HS;
#pragma unroll
        for (int hnt = 0; hnt < 4; hnt++) {
            int col = hnt * 8 + qc;
            *(float2*)(oa + col) = make_float2(oacc[hnt][0] * rinv1, oacc[hnt][1] * rinv1);
            *(float2*)(ob + col) = make_float2(oacc[hnt][2] * rinv2, oacc[hnt][3] * rinv2);
        }
    } else {
        // write partials, then the LAST block of this (tile,b) group combines
        float* pa = g_pacc + ((size_t)slot * NROWS + r1g) * HS;
        float* pb = g_pacc + ((size_t)slot * NROWS + r2g) * HS;
#pragma unroll
        for (int hnt = 0; hnt < 4; hnt++) {
            int col = hnt * 8 + qc;
            *(float2*)(pa + col) = make_float2(oacc[hnt][0], oacc[hnt][1]);
            *(float2*)(pb + col) = make_float2(oacc[hnt][2], oacc[hnt][3]);
        }
        if ((lane & 3) == 0) {
            g_pden[r1g * 4 + slot] = den1;
            g_pden[r2g * 4 + slot] = den2;
        }
        __threadfence();
        __syncthreads();
        int nch = (tile >> 2) + 1;
        if (tid == 0) {
            int n = atomicAdd(&g_cnt[(b << 4) + tile], 1);
            s_last = (n == nch - 1);
        }
        __syncthreads();
        if (s_last) {
            const float4* pacc4 = (const float4*)g_pacc;
            for (int i = tid; i < 1024; i += 256) {
                int rl = i >> 3, q = i & 7;
                size_t row = (size_t)b * TT + t0 + rl;
                float4 dv = __ldcg((const float4*)(g_pden + row * 4));
                float4 v0 = __ldcg(pacc4 + row * 8 + q);
                float4 v1 = __ldcg(pacc4 + ((size_t)1 * NROWS + row) * 8 + q);
                float4 v2 = (nch > 2) ? __ldcg(pacc4 + ((size_t)2 * NROWS + row) * 8 + q)
                                      : make_float4(0.f, 0.f, 0.f, 0.f);
                float4 v3 = (nch > 3) ? __ldcg(pacc4 + ((size_t)3 * NROWS + row) * 8 + q)
                                      : make_float4(0.f, 0.f, 0.f, 0.f);
                float den = dv.x + dv.y;
                if (nch > 2) den += dv.z;
                if (nch > 3) den += dv.w;
                float rinv = 1.f / den;
                float4 a;
                a.x = ((v0.x + v1.x) + (v2.x + v3.x)) * rinv;
                a.y = ((v0.y + v1.y) + (v2.y + v3.y)) * rinv;
                a.z = ((v0.z + v1.z) + (v2.z + v3.z)) * rinv;
                a.w = ((v0.w + v1.w) + (v2.w + v3.w)) * rinv;
                ((float4*)out)[row * 8 + q] = a;
            }
        }
    }
}

extern "C" void kernel_launch(void* const* d_in, const int* in_sizes, int n_in,
                              void* d_out, int out_size) {
    const float* x  = (const float*)d_in[0];
    const float* Wk = (const float*)d_in[1];
    const float* Wq = (const float*)d_in[2];
    const float* Wv = (const float*)d_in[3];
    float* out = (float*)d_out;

    prepack_kernel<<<(3 * NKS * 32 * 4 + 255) / 256, 256>>>(Wk, Wq, Wv);

    cudaFuncSetAttribute(proj_mma, cudaFuncAttributeMaxDynamicSharedMemorySize, PSM);
    proj_mma<<<NROWS / 64, 256, PSM>>>(x);

    cudaFuncSetAttribute(attn_mma, cudaFuncAttributeMaxDynamicSharedMemorySize, SMEMB);
    attn_mma<<<640, 256, SMEMB>>>(out);
}

// round 17
// speedup vs baseline: 1.0455x; 1.0455x over previous
#include <cuda_runtime.h>
#include <cuda_bf16.h>
#include <cuda_fp16.h>

#define BB 16
#define TT 2048
#define CC 288
#define HS 32
#define NROWS (BB*TT)
#define NKS (CC/16)
#define QKSCALE 0.17677669529663687f

typedef unsigned long long u64;
typedef unsigned int u32;

// ---- scratch (device globals; cudaMalloc forbidden) ----
__device__ __align__(16) __nv_bfloat16 g_kspl[NROWS*64];
__device__ __align__(16) __nv_bfloat16 g_qspl[NROWS*64];
__device__ __align__(16) __half g_vth[BB*HS*TT];   // V^T (fp16, single precision level)
__device__ u64 g_wbh[3*NKS*32*4];
__device__ u64 g_wbl[3*NKS*32*4];
__device__ float g_pacc[(size_t)4*NROWS*HS];   // split-s partial P.V
__device__ float g_pden[NROWS*4];              // [row][slot] partial sum(exp)
__device__ int   g_cnt[256];                   // [b][tile] completion counters

__device__ __forceinline__ u32 packbf(__nv_bfloat16 a, __nv_bfloat16 b) {
    return ((u32)__bfloat16_as_ushort(b) << 16) | (u32)__bfloat16_as_ushort(a);
}
__device__ __forceinline__ u32 smem_u32(const void* p) {
    u32 a; asm("{ .reg .u64 t; cvta.to.shared.u64 t, %1; cvt.u32.u64 %0, t; }" : "=r"(a) : "l"(p));
    return a;
}
__device__ __forceinline__ u32 cvt2f16(float hi, float lo) {
    u32 r; asm("cvt.rn.f16x2.f32 %0,%1,%2;" : "=r"(r) : "f"(hi), "f"(lo)); return r;
}
__device__ __forceinline__ void mma_bf16(float* d, const u32* a, const u32* b) {
    asm volatile(
        "mma.sync.aligned.m16n8k16.row.col.f32.bf16.bf16.f32 "
        "{%0,%1,%2,%3}, {%4,%5,%6,%7}, {%8,%9}, {%0,%1,%2,%3};"
        : "+f"(d[0]), "+f"(d[1]), "+f"(d[2]), "+f"(d[3])
        : "r"(a[0]), "r"(a[1]), "r"(a[2]), "r"(a[3]), "r"(b[0]), "r"(b[1]));
}
__device__ __forceinline__ void mma_fp16(float* d, const u32* a, const u32* b) {
    asm volatile(
        "mma.sync.aligned.m16n8k16.row.col.f32.f16.f16.f32 "
        "{%0,%1,%2,%3}, {%4,%5,%6,%7}, {%8,%9}, {%0,%1,%2,%3};"
        : "+f"(d[0]), "+f"(d[1]), "+f"(d[2]), "+f"(d[3])
        : "r"(a[0]), "r"(a[1]), "r"(a[2]), "r"(a[3]), "r"(b[0]), "r"(b[1]));
}
__device__ __forceinline__ void ldsm4(u32& r0, u32& r1, u32& r2, u32& r3, u32 addr) {
    asm volatile("ldmatrix.sync.aligned.m8n8.x4.shared.b16 {%0,%1,%2,%3}, [%4];"
                 : "=r"(r0), "=r"(r1), "=r"(r2), "=r"(r3) : "r"(addr));
}
__device__ __forceinline__ void cpa16(u32 dst, const void* src) {
    asm volatile("cp.async.cg.shared.global [%0], [%1], 16;" :: "r"(dst), "l"(src));
}
#define CPCOMMIT() asm volatile("cp.async.commit_group;" ::: "memory")
#define CPWAIT0()  asm volatile("cp.async.wait_group 0;" ::: "memory")

// ---- (tile, chunk<<8) worklist: heavy 4-unit chunks first. Flat grid 640:
// wave 1 = heavy blocks only, wave 2 = light partials.
static __device__ const int g_pairs[40] = {
    15, 15|256, 15|512, 15|768,
    14, 14|256, 14|512,
    13, 13|256, 13|512,
    12, 12|256, 12|512,
    11, 11|256, 11|512,
    10, 10|256, 9, 9|256, 8, 8|256, 7, 7|256,
    6, 5, 4, 3,
    14|768, 10|512, 6|256, 2,
    13|768, 9|512, 5|256, 1,
    12|768, 8|512, 4|256, 0
};

// -------------------------------------------------------------------------
// Prepack: W -> bf16 hi/lo B-fragment u64s + zero combine counters.
// -------------------------------------------------------------------------
__global__ void prepack_kernel(const float* __restrict__ Wk,
                               const float* __restrict__ Wq,
                               const float* __restrict__ Wv) {
    if (blockIdx.x == 0) g_cnt[threadIdx.x] = 0;
    int i = blockIdx.x * 256 + threadIdx.x;
    if (i >= 3 * NKS * 32 * 4) return;
    int tig = i & 3;
    int n = (i >> 2) & 31;
    int ks = (i >> 7) % NKS;
    int p = i / (NKS * 32 * 4);
    const float* W = (p == 0) ? Wk : (p == 1) ? Wq : Wv;
    float s = (p == 0) ? QKSCALE : 1.0f;
    int c0 = ks * 16 + tig * 2;
    float w[4];
    w[0] = W[(c0)     * HS + n] * s;
    w[1] = W[(c0 + 1) * HS + n] * s;
    w[2] = W[(c0 + 8) * HS + n] * s;
    w[3] = W[(c0 + 9) * HS + n] * s;
    __nv_bfloat16 h[4]; float l[4];
#pragma unroll
    for (int j = 0; j < 4; j++) { h[j] = __float2bfloat16(w[j]); l[j] = w[j] - __bfloat162float(h[j]); }
    g_wbh[i] = ((u64)packbf(h[2], h[3]) << 32) | (u64)packbf(h[0], h[1]);
    g_wbl[i] = ((u64)packbf(__float2bfloat16(l[2]), __float2bfloat16(l[3])) << 32)
             | (u64)packbf(__float2bfloat16(l[0]), __float2bfloat16(l[1]));
}

// -------------------------------------------------------------------------
// Tensor-core projection. K/Q bf16 hi/lo; V single fp16 (lo term dropped).
// -------------------------------------------------------------------------
#define XSTR 296
#define PSM (64*XSTR*2*2)

__global__ void __launch_bounds__(256, 3) proj_mma(const float* __restrict__ x) {
    extern __shared__ __nv_bfloat16 psm[];
    __nv_bfloat16* xhi = psm;
    __half* vsh = (__half*)psm;          // aliases x region (dead after MMA loop)

    int tid = threadIdx.x;
    int row0 = blockIdx.x * 64;

    {
        const float4* xg = (const float4*)(x + (size_t)row0 * CC);
        for (int i = tid; i < 64 * 72; i += 256) {
            int row = i / 72, c4 = i % 72;
            float4 v = xg[i];
            __nv_bfloat16 h0 = __float2bfloat16(v.x), h1 = __float2bfloat16(v.y);
            __nv_bfloat16 h2 = __float2bfloat16(v.z), h3 = __float2bfloat16(v.w);
            *(uint2*)(xhi + row * XSTR + c4 * 4) =
                make_uint2(packbf(h0, h1), packbf(h2, h3));
            *(uint2*)(xhi + (64 + row) * XSTR + c4 * 4) = make_uint2(
                packbf(__float2bfloat16(v.x - __bfloat162float(h0)),
                       __float2bfloat16(v.y - __bfloat162float(h1))),
                packbf(__float2bfloat16(v.z - __bfloat162float(h2)),
                       __float2bfloat16(v.w - __bfloat162float(h3))));
        }
    }
    __syncthreads();

    int wid = tid >> 5, lane = tid & 31;
    int g = lane >> 2, tig = lane & 3;
    int rs = wid & 3, half = wid >> 2;
    int lr = lane & 7, lm = lane >> 3;

    u32 smb = smem_u32(psm);
    u32 xh_b = smb + (u32)(((rs * 16 + lr + (lm & 1) * 8) * XSTR + (lm >> 1) * 8) * 2);
    u32 xl_b = xh_b + (u32)(64 * XSTR * 2);

    int ou[6];
#pragma unroll
    for (int u = 0; u < 6; u++) {
        int idx = half * 6 + u;
        int p = idx >> 2, nt = idx & 3;
        ou[u] = ((p * NKS) * 32 + nt * 8 + g) * 4 + tig;
    }

    float oacc[6][4];
#pragma unroll
    for (int u = 0; u < 6; u++)
#pragma unroll
        for (int j = 0; j < 4; j++) oacc[u][j] = 0.f;

    for (int ks = 0; ks < NKS; ks++) {
        u32 ah[4], al[4];
        ldsm4(ah[0], ah[1], ah[2], ah[3], xh_b + (u32)(ks * 32));
        ldsm4(al[0], al[1], al[2], al[3], xl_b + (u32)(ks * 32));
        int o2 = ks * 128;
#pragma unroll
        for (int u = 0; u < 6; u++) {
            u64 wh = g_wbh[ou[u] + o2];
            u64 wl = g_wbl[ou[u] + o2];
            u32 bh[2] = { (u32)wh, (u32)(wh >> 32) };
            u32 bl[2] = { (u32)wl, (u32)(wl >> 32) };
            mma_bf16(oacc[u], ah, bh);
            mma_bf16(oacc[u], al, bh);
            mma_bf16(oacc[u], ah, bl);
        }
    }
    __syncthreads();   // x region dead; vsh aliases it below

#pragma unroll
    for (int u = 0; u < 6; u++) {
        int idx = half * 6 + u;
        int p = idx >> 2, nt = idx & 3;
        int c0 = nt * 8 + 2 * tig;
        int rloc0 = rs * 16 + g;
#pragma unroll
        for (int rr = 0; rr < 2; rr++) {
            int rloc = rloc0 + rr * 8;
            float v0 = oacc[u][rr * 2], v1 = oacc[u][rr * 2 + 1];
            if (p == 0) {
                __nv_bfloat16 h0 = __float2bfloat16(v0), h1 = __float2bfloat16(v1);
                size_t r = (size_t)(row0 + rloc) * 64;
                *(u32*)(g_kspl + r + c0) = packbf(h0, h1);
                *(u32*)(g_kspl + r + 32 + c0) =
                    packbf(__float2bfloat16(v0 - __bfloat162float(h0)),
                           __float2bfloat16(v1 - __bfloat162float(h1)));
            } else if (p == 1) {
                __nv_bfloat16 h0 = __float2bfloat16(v0), h1 = __float2bfloat16(v1);
                size_t r = (size_t)(row0 + rloc) * 64;
                *(u32*)(g_qspl + r + c0) = packbf(h0, h1);
                *(u32*)(g_qspl + r + 32 + c0) =
                    packbf(__float2bfloat16(v0 - __bfloat162float(h0)),
                           __float2bfloat16(v1 - __bfloat162float(h1)));
            } else {
                vsh[c0 * 64 + rloc] = __float2half_rn(v0);
                vsh[(c0 + 1) * 64 + rloc] = __float2half_rn(v1);
            }
        }
    }
    __syncthreads();
    {
        int b = row0 >> 11, tin = row0 & (TT - 1);
        int h = tid >> 3, seg = tid & 7;
        size_t gb = ((size_t)(b * HS + h)) * TT + tin + seg * 8;
        *(uint4*)(g_vth + gb) = *(const uint4*)(vsh + h * 64 + seg * 8);
    }
}

// -------------------------------------------------------------------------
// Flash attention: QK bf16 3-split, PV fp16 single (V-lo dropped -> 1 MMA).
// Split-s + cp.async double buffering; Q1 aliases K region (53 KB, 3 CTA/SM).
// Single-chunk tiles write out directly; multi-chunk groups reduce in the
// LAST-arriving block (atomic counter, __ldcg reads).
// smem (elems): [K/Q1: 9216][Q0: 9216][V0: 4352][V1: 4352]
// -------------------------------------------------------------------------
#define KSTR 72
#define VSTR 136
#define QOFS0 9216
#define QOFS1 0
#define VB0   18432
#define VBSZ  4352
#define SMEMB (27136 * 2)

__device__ __forceinline__ void load_tile_async(u32 smb, int buf, int b, int s0, int tid) {
    const uint4* qg = (const uint4*)(g_qspl + ((size_t)(b * TT + s0)) * 64);
    u32 qb = smb + (buf ? (u32)(QOFS1 * 2) : (u32)(QOFS0 * 2));
#pragma unroll
    for (int k = 0; k < 4; k++) {
        int i = tid + k * 256;
        int row = i >> 3, seg = i & 7;
        cpa16(qb + (u32)((row * KSTR + seg * 8) * 2), qg + i);
    }
    u32 vhb = smb + (u32)((VB0 + buf * VBSZ) * 2);
#pragma unroll
    for (int k = 0; k < 2; k++) {
        int i = tid + k * 256;
        int row = i >> 4, seg = i & 15;
        size_t base = ((size_t)(b * HS + row)) * TT + s0;
        cpa16(vhb + (u32)((row * VSTR + seg * 8) * 2), ((const uint4*)(g_vth + base)) + seg);
    }
}

__global__ void __launch_bounds__(256, 3) attn_mma(float* __restrict__ out) {
    extern __shared__ __nv_bfloat16 sm[];
    __shared__ int s_last;
    __nv_bfloat16* ks = sm;        // K region; becomes Q buffer 1

    int pr = g_pairs[blockIdx.x >> 4];
    int b = blockIdx.x & 15;
    int tile = pr & 0xff;
    int slot = pr >> 8;

    int tid = threadIdx.x, wid = tid >> 5, lane = tid & 31;
    int qr = lane >> 2, qc = (lane & 3) << 1;
    int lr = lane & 7, lm = lane >> 3;
    int t0 = tile << 7;
    int r1 = (wid << 4) + qr;
    int trow1 = t0 + r1, trow2 = trow1 + 8;

    u32 smb = smem_u32(sm);
    u32 qcol2 = (lm == 0) ? 0u : (lm == 1) ? 16u : (lm == 2) ? 64u : 80u;
    u32 qlb_off = (u32)(lr * KSTR * 2) + qcol2;
    // V ldsm x4: m0/m1 = k-slice j=0 (cols 0-7, 8-15), m2/m3 = j=1 (16-23, 24-31)
    u32 vlb_off = (u32)(lr * VSTR * 2) + (u32)(lm * 16);

    int st_beg = slot * 4;
    int st_end = st_beg + 4;
    if (st_end > tile + 1) st_end = tile + 1;
    int nst = st_end - st_beg;
    bool fullrow = (st_beg == 0) && (st_end == tile + 1);

    // ---- K tile + first Q/V tile async ----
    {
        const uint4* kg = (const uint4*)(g_kspl + ((size_t)(b * TT + t0)) * 64);
        for (int i = tid; i < 1024; i += 256) {
            int row = i >> 3, seg = i & 7;
            *(uint4*)(ks + row * KSTR + seg * 8) = kg[row * 8 + seg];
        }
    }
    load_tile_async(smb, 0, b, st_beg << 7, tid);
    CPCOMMIT();
    __syncthreads();

    u32 aK[2][2][4];
#pragma unroll
    for (int sp = 0; sp < 2; sp++)
#pragma unroll
        for (int kk = 0; kk < 2; kk++) {
            int c = sp * 32 + kk * 16 + qc;
            aK[sp][kk][0] = *(const u32*)(ks + r1 * KSTR + c);
            aK[sp][kk][1] = *(const u32*)(ks + (r1 + 8) * KSTR + c);
            aK[sp][kk][2] = *(const u32*)(ks + r1 * KSTR + c + 8);
            aK[sp][kk][3] = *(const u32*)(ks + (r1 + 8) * KSTR + c + 8);
        }

    float oacc[4][4];
#pragma unroll
    for (int i = 0; i < 4; i++)
#pragma unroll
        for (int j = 0; j < 4; j++) oacc[i][j] = 0.f;
    float den1 = 0.f, den2 = 0.f;

    for (int it = 0; it < nst; it++) {
        int st = st_beg + it;
        int cur = it & 1;
        CPWAIT0();
        __syncthreads();
        if (it + 1 < nst) {
            load_tile_async(smb, cur ^ 1, b, (st + 1) << 7, tid);
            CPCOMMIT();
        }
        u32 qlb = smb + (cur ? (u32)(QOFS1 * 2) : (u32)(QOFS0 * 2)) + qlb_off;
        u32 vlb = smb + (u32)((VB0 + cur * VBSZ) * 2) + vlb_off;

        bool diag = (st == tile);
#pragma unroll 1
        for (int ch = 0; ch < 4; ch++) {
            float sacc[4][4];
#pragma unroll
            for (int i = 0; i < 4; i++)
#pragma unroll
                for (int j = 0; j < 4; j++) sacc[i][j] = 0.f;
#pragma unroll
            for (int kk = 0; kk < 2; kk++) {
#pragma unroll
                for (int nt = 0; nt < 4; nt++) {
                    u32 b0, b1, b2, b3;
                    ldsm4(b0, b1, b2, b3,
                          qlb + (u32)((((ch * 32 + nt * 8) * KSTR) + kk * 16) * 2));
                    u32 bh[2] = { b0, b1 }, bl[2] = { b2, b3 };
                    mma_bf16(sacc[nt], aK[0][kk], bh);
                    mma_bf16(sacc[nt], aK[1][kk], bh);
                    mma_bf16(sacc[nt], aK[0][kk], bl);
                }
            }
            u32 pha[2][4];
            int scb = (st << 7) + ch * 32;
#pragma unroll
            for (int nt = 0; nt < 4; nt++) {
                int c0 = scb + nt * 8 + qc;
                float p0, p1, p2, p3;
                if (diag) {
                    p0 = (c0     <= trow1) ? __expf(sacc[nt][0]) : 0.f;
                    p1 = (c0 + 1 <= trow1) ? __expf(sacc[nt][1]) : 0.f;
                    p2 = (c0     <= trow2) ? __expf(sacc[nt][2]) : 0.f;
                    p3 = (c0 + 1 <= trow2) ? __expf(sacc[nt][3]) : 0.f;
                } else {
                    p0 = __expf(sacc[nt][0]);
                    p1 = __expf(sacc[nt][1]);
                    p2 = __expf(sacc[nt][2]);
                    p3 = __expf(sacc[nt][3]);
                }
                den1 += p0 + p1;
                den2 += p2 + p3;
                int j = nt >> 1, o = (nt & 1) << 1;
                pha[j][o]     = cvt2f16(p1, p0);
                pha[j][o + 1] = cvt2f16(p3, p2);
            }
            // ---- O += P.V : one ldsm4 covers both j-slices of V ----
#pragma unroll
            for (int hnt = 0; hnt < 4; hnt++) {
                u32 b0, b1, b2, b3;
                ldsm4(b0, b1, b2, b3,
                      vlb + (u32)((hnt * 8 * VSTR + ch * 32) * 2));
                u32 bj0[2] = { b0, b1 }, bj1[2] = { b2, b3 };
                mma_fp16(oacc[hnt], pha[0], bj0);
                mma_fp16(oacc[hnt], pha[1], bj1);
            }
        }
    }

    den1 += __shfl_xor_sync(0xffffffffu, den1, 1);
    den1 += __shfl_xor_sync(0xffffffffu, den1, 2);
    den2 += __shfl_xor_sync(0xffffffffu, den2, 1);
    den2 += __shfl_xor_sync(0xffffffffu, den2, 2);

    size_t r1g = (size_t)b * TT + trow1;
    size_t r2g = (size_t)b * TT + trow2;
    if (fullrow) {
        float rinv1 = 1.f / den1, rinv2 = 1.f / den2;
        float* oa = out + r1g * HS;
        float* ob = out + r2g * HS;
#pragma unroll
        for (int hnt = 0; hnt < 4; hnt++) {
            int col = hnt * 8 + qc;
            *(float2*)(oa + col) = make_float2(oacc[hnt][0] * rinv1, oacc[hnt][1] * rinv1);
            *(float2*)(ob + col) = make_float2(oacc[hnt][2] * rinv2, oacc[hnt][3] * rinv2);
        }
    } else {
        float* pa = g_pacc + ((size_t)slot * NROWS + r1g) * HS;
        float* pb = g_pacc + ((size_t)slot * NROWS + r2g) * HS;
#pragma unroll
        for (int hnt = 0; hnt < 4; hnt++) {
            int col = hnt * 8 + qc;
            *(float2*)(pa + col) = make_float2(oacc[hnt][0], oacc[hnt][1]);
            *(float2*)(pb + col) = make_float2(oacc[hnt][2], oacc[hnt][3]);
        }
        if ((lane & 3) == 0) {
            g_pden[r1g * 4 + slot] = den1;
            g_pden[r2g * 4 + slot] = den2;
        }
        __threadfence();
        __syncthreads();
        int nch = (tile >> 2) + 1;
        if (tid == 0) {
            int n = atomicAdd(&g_cnt[(b << 4) + tile], 1);
            s_last = (n == nch - 1);
        }
        __syncthreads();
        if (s_last) {
            const float4* pacc4 = (const float4*)g_pacc;
            for (int i = tid; i < 1024; i += 256) {
                int rl = i >> 3, q = i & 7;
                size_t row = (size_t)b * TT + t0 + rl;
                float4 dv = __ldcg((const float4*)(g_pden + row * 4));
                float4 v0 = __ldcg(pacc4 + row * 8 + q);
                float4 v1 = __ldcg(pacc4 + ((size_t)1 * NROWS + row) * 8 + q);
                float4 v2 = (nch > 2) ? __ldcg(pacc4 + ((size_t)2 * NROWS + row) * 8 + q)
                                      : make_float4(0.f, 0.f, 0.f, 0.f);
                float4 v3 = (nch > 3) ? __ldcg(pacc4 + ((size_t)3 * NROWS + row) * 8 + q)
                                      : make_float4(0.f, 0.f, 0.f, 0.f);
                float den = dv.x + dv.y;
                if (nch > 2) den += dv.z;
                if (nch > 3) den += dv.w;
                float rinv = 1.f / den;
                float4 a;
                a.x = ((v0.x + v1.x) + (v2.x + v3.x)) * rinv;
                a.y = ((v0.y + v1.y) + (v2.y + v3.y)) * rinv;
                a.z = ((v0.z + v1.z) + (v2.z + v3.z)) * rinv;
                a.w = ((v0.w + v1.w) + (v2.w + v3.w)) * rinv;
                ((float4*)out)[row * 8 + q] = a;
            }
        }
    }
}

extern "C" void kernel_launch(void* const* d_in, const int* in_sizes, int n_in,
                              void* d_out, int out_size) {
    const float* x  = (const float*)d_in[0];
    const float* Wk = (const float*)d_in[1];
    const float* Wq = (const float*)d_in[2];
    const float* Wv = (const float*)d_in[3];
    float* out = (float*)d_out;

    prepack_kernel<<<(3 * NKS * 32 * 4 + 255) / 256, 256>>>(Wk, Wq, Wv);

    cudaFuncSetAttribute(proj_mma, cudaFuncAttributeMaxDynamicSharedMemorySize, PSM);
    proj_mma<<<NROWS / 64, 256, PSM>>>(x);

    cudaFuncSetAttribute(attn_mma, cudaFuncAttributeMaxDynamicSharedMemorySize, SMEMB);
    attn_mma<<<640, 256, SMEMB>>>(out);
}